// round 14
// baseline (speedup 1.0000x reference)
#include <cuda_runtime.h>
#include <cuda_fp16.h>
#include <math_constants.h>
#include <cstdint>

#define BB    32
#define NN    512
#define DIN_  768
#define DOUT_ 256
#define MROWS (BB * NN)          // 16384
#define NEGV  (-9.0e15f)
#define SLOPE 0.2f

// Scratch (device globals: allocation-free)
__device__ float g_s1[MROWS];
__device__ float g_s2[MROWS];
__device__ __half g_WTf[DOUT_ * DIN_];   // W^T fp16, [256][768] K-major
__device__ __half g_Whf[MROWS * DOUT_];  // Wh fp16,  [row][d]     8 MB

// ---------------------------------------------------------------------------
// Helpers
// ---------------------------------------------------------------------------
__device__ __forceinline__ uint32_t smem_u32(const void* p) {
    uint32_t a;
    asm("{ .reg .u64 t; cvta.to.shared.u64 t, %1; cvt.u32.u64 %0, t; }"
        : "=r"(a) : "l"(p));
    return a;
}

#define LDSM_X4(r, addr)                                                      \
    asm volatile("ldmatrix.sync.aligned.m8n8.x4.shared.b16 {%0,%1,%2,%3}, [%4];" \
                 : "=r"((r)[0]), "=r"((r)[1]), "=r"((r)[2]), "=r"((r)[3])     \
                 : "r"(addr))
#define LDSM_X4_T(r, addr)                                                    \
    asm volatile("ldmatrix.sync.aligned.m8n8.x4.trans.shared.b16 {%0,%1,%2,%3}, [%4];" \
                 : "=r"((r)[0]), "=r"((r)[1]), "=r"((r)[2]), "=r"((r)[3])     \
                 : "r"(addr))

__device__ __forceinline__ void mma16816(float* c, const uint32_t* a,
                                         uint32_t b0, uint32_t b1) {
    asm volatile(
        "mma.sync.aligned.m16n8k16.row.col.f32.f16.f16.f32 "
        "{%0,%1,%2,%3}, {%4,%5,%6,%7}, {%8,%9}, {%0,%1,%2,%3};"
        : "+f"(c[0]), "+f"(c[1]), "+f"(c[2]), "+f"(c[3])
        : "r"(a[0]), "r"(a[1]), "r"(a[2]), "r"(a[3]), "r"(b0), "r"(b1));
}

#define CP_ASYNC16(dst, src) \
    asm volatile("cp.async.cg.shared.global [%0], [%1], 16;" :: "r"(dst), "l"(src))
#define CP_COMMIT()  asm volatile("cp.async.commit_group;" ::: "memory")
#define CP_WAIT0()   asm volatile("cp.async.wait_group 0;" ::: "memory")
#define CP_WAIT2()   asm volatile("cp.async.wait_group 2;" ::: "memory")

__device__ __forceinline__ uint32_t pack_h2(__half a, __half b) {
    __half2 t(a, b);
    return *(uint32_t*)&t;
}

// ---------------------------------------------------------------------------
// Kernel 0: W [768,256] fp32 -> W^T fp16 [256][768] via smem tile transpose.
// 64k x 64n tiles, grid (12, 4), 256 threads. Coalesced reads and writes.
// ---------------------------------------------------------------------------
__global__ void wt_convert_kernel(const float* __restrict__ W) {
    __shared__ __half st[64][72];   // [n][k], padded
    const int tid = threadIdx.x;
    const int k0 = blockIdx.x * 64;
    const int n0 = blockIdx.y * 64;

#pragma unroll
    for (int i = 0; i < 4; i++) {
        const int e = tid + i * 256;          // 0..1023
        const int r  = e >> 4;                // k-row 0..63
        const int c4 = (e & 15) * 4;          // n-col 0..60
        const float4 v = *(const float4*)&W[(size_t)(k0 + r) * DOUT_ + n0 + c4];
        st[c4 + 0][r] = __float2half(v.x);
        st[c4 + 1][r] = __float2half(v.y);
        st[c4 + 2][r] = __float2half(v.z);
        st[c4 + 3][r] = __float2half(v.w);
    }
    __syncthreads();

#pragma unroll
    for (int i = 0; i < 2; i++) {
        const int e = tid + i * 256;          // 0..511
        const int n   = e >> 3;               // 0..63
        const int seg = e & 7;                // 0..7 (8 halves each)
        uint4 v;
        const __half* src = &st[n][seg * 8];
        v.x = *(const uint32_t*)&src[0];
        v.y = *(const uint32_t*)&src[2];
        v.z = *(const uint32_t*)&src[4];
        v.w = *(const uint32_t*)&src[6];
        *(uint4*)&g_WTf[(size_t)(n0 + n) * DIN_ + k0 + seg * 8] = v;
    }
}

// ---------------------------------------------------------------------------
// Kernel 1: Wh = h @ W + pos_table[positions] (fp16 mma.sync), FULL N=256
// per block: tile 128m x 256n, 512 threads (16 warps: 4m x 4n, warp tile
// 32x64 -- identical inner loop to the proven 8-warp version). Grid 128 =
// single wave; h is read exactly once. s1/s2 complete in-block via smem
// reduction + plain stores (no atomics, no zero-init dependency).
//
// smem per buffer: A [128][40]h @0 (10240 B), B [256][40]h @10240 (20480 B)
// buf stride 30720; 2 bufs; s1/s2 reduce arrays @61440 (1024 B). Tot 62464.
// ---------------------------------------------------------------------------
#define PAD    40
#define CHUNK  32
#define NCHK   (DIN_ / CHUNK)     // 24
#define BUF_B  30720
#define RED_O  61440
#define GSMEM  62464

extern __shared__ char smem_g[];

__device__ __forceinline__ void load_A_regs(const float* __restrict__ h,
                                            int m0, int kbase, int tid,
                                            float4* aR) {
#pragma unroll
    for (int i = 0; i < 2; i++) {
        const int e = tid + i * 512;          // 0..1023
        const int row = e >> 3;               // 0..127
        const int c4  = (e & 7) * 4;          // 0..28
        aR[i] = *(const float4*)&h[(size_t)(m0 + row) * DIN_ + kbase + c4];
    }
}

__device__ __forceinline__ void store_A_smem(char* s, int tid, const float4* aR) {
#pragma unroll
    for (int i = 0; i < 2; i++) {
        const int e = tid + i * 512;
        const int row = e >> 3;
        const int c4  = (e & 7) * 4;
        const float4 v = aR[i];
        uint2 hv;
        hv.x = pack_h2(__float2half(v.x), __float2half(v.y));
        hv.y = pack_h2(__float2half(v.z), __float2half(v.w));
        *(uint2*)(s + (uint32_t)(row * (PAD * 2) + c4 * 2)) = hv;
    }
}

__device__ __forceinline__ void cpasync_B(uint32_t b_byte, int kbase, int tid) {
#pragma unroll
    for (int i = 0; i < 2; i++) {
        const int e = tid + i * 512;          // 0..1023
        const int row = e >> 2;               // 0..255
        const int q   = e & 3;                // 0..3
        const size_t gi = (size_t)row * DIN_ + kbase + q * 8;
        CP_ASYNC16(b_byte + (uint32_t)(row * (PAD * 2) + q * 16),
                   (const void*)&g_WTf[gi]);
    }
}

__global__ __launch_bounds__(512, 1)
void gemm_wh_mma_kernel(const float* __restrict__ h,
                        const int*   __restrict__ positions,
                        const float* __restrict__ pos_table,
                        const float* __restrict__ a1,
                        const float* __restrict__ a2) {
    const uint32_t sb = smem_u32(smem_g);
    const int tid  = threadIdx.x;
    const int wid  = tid >> 5;
    const int lane = tid & 31;
    const int wm = wid >> 2;           // 0..3
    const int wn = wid & 3;            // 0..3
    const int m0 = blockIdx.x * 128;

    const int lr = lane & 15;
    const int lk = (lane >> 4) * 8;
    const int bn = ((lane >> 4) * 8) + (lane & 7);
    const int bk = ((lane >> 3) & 1) * 8;

    float acc[2][8][4];
#pragma unroll
    for (int mi = 0; mi < 2; mi++)
#pragma unroll
        for (int ni = 0; ni < 8; ni++)
#pragma unroll
            for (int q = 0; q < 4; q++) acc[mi][ni][q] = 0.f;

    float4 aR[2];

    cpasync_B(sb + 10240, 0, tid);
    CP_COMMIT();
    load_A_regs(h, m0, 0, tid, aR);
    store_A_smem(smem_g, tid, aR);
    CP_WAIT0();
    __syncthreads();

    for (int c = 0; c < NCHK; c++) {
        const int buf  = c & 1;
        const int nbuf = buf ^ 1;

        if (c < NCHK - 1) {
            const int kn = (c + 1) * CHUNK;
            cpasync_B(sb + nbuf * BUF_B + 10240, kn, tid);
            CP_COMMIT();
            load_A_regs(h, m0, kn, tid, aR);
        }

        const uint32_t AS = sb + buf * BUF_B;
        const uint32_t BS = AS + 10240;

#pragma unroll
        for (int k16 = 0; k16 < CHUNK; k16 += 16) {
            uint32_t ah[2][4];
#pragma unroll
            for (int mi = 0; mi < 2; mi++) {
                const uint32_t aa =
                    AS + (uint32_t)(((wm * 32 + mi * 16 + lr) * PAD + k16 + lk) * 2);
                LDSM_X4(ah[mi], aa);
            }
#pragma unroll
            for (int g = 0; g < 4; g++) {
                const uint32_t ba =
                    BS + (uint32_t)(((wn * 64 + g * 16 + bn) * PAD + k16 + bk) * 2);
                uint32_t bh[4];
                LDSM_X4(bh, ba);
#pragma unroll
                for (int mi = 0; mi < 2; mi++) {
                    mma16816(acc[mi][2 * g],     ah[mi], bh[0], bh[1]);
                    mma16816(acc[mi][2 * g + 1], ah[mi], bh[2], bh[3]);
                }
            }
        }

        if (c < NCHK - 1) store_A_smem(smem_g + nbuf * BUF_B, tid, aR);
        CP_WAIT0();
        __syncthreads();
    }

    // Zero the s1/s2 reduction arrays.
    float* s_red1 = (float*)(smem_g + RED_O);          // [128]
    float* s_red2 = (float*)(smem_g + RED_O + 512);    // [128]
    if (tid < 128) { s_red1[tid] = 0.f; s_red2[tid] = 0.f; }
    __syncthreads();

    // Epilogue: add pos_emb; store fp16 Wh; partial s1/s2 dots.
    const int g = lane >> 2, t = lane & 3;
    float p1[2][2], p2[2][2];
#pragma unroll
    for (int mi = 0; mi < 2; mi++)
#pragma unroll
        for (int h2 = 0; h2 < 2; h2++) { p1[mi][h2] = 0.f; p2[mi][h2] = 0.f; }

#pragma unroll
    for (int mi = 0; mi < 2; mi++) {
#pragma unroll
        for (int h2 = 0; h2 < 2; h2++) {
            const int row = m0 + wm * 32 + mi * 16 + g + h2 * 8;
            const int pos = positions[row];
            const float* pt = &pos_table[(size_t)pos * DOUT_];
#pragma unroll
            for (int ni = 0; ni < 8; ni++) {
                const int col = wn * 64 + ni * 8 + t * 2;
                const float2 p = *(const float2*)&pt[col];
                const float ox = acc[mi][ni][h2 * 2 + 0] + p.x;
                const float oy = acc[mi][ni][h2 * 2 + 1] + p.y;
                *(uint32_t*)&g_Whf[(size_t)row * DOUT_ + col] =
                    pack_h2(__float2half(ox), __float2half(oy));
                const float2 va1 = *(const float2*)&a1[col];
                const float2 va2 = *(const float2*)&a2[col];
                p1[mi][h2] += ox * va1.x + oy * va1.y;
                p2[mi][h2] += ox * va2.x + oy * va2.y;
            }
        }
    }
    // Reduce over the 4 t-lanes, then across the 4 wn-warps via smem atomics.
#pragma unroll
    for (int mi = 0; mi < 2; mi++)
#pragma unroll
        for (int h2 = 0; h2 < 2; h2++) {
            float v1 = p1[mi][h2], v2 = p2[mi][h2];
            v1 += __shfl_xor_sync(0xFFFFFFFFu, v1, 1);
            v1 += __shfl_xor_sync(0xFFFFFFFFu, v1, 2);
            v2 += __shfl_xor_sync(0xFFFFFFFFu, v2, 1);
            v2 += __shfl_xor_sync(0xFFFFFFFFu, v2, 2);
            if (t == 0) {
                const int lrow = wm * 32 + mi * 16 + g + h2 * 8;   // 0..127
                atomicAdd(&s_red1[lrow], v1);
                atomicAdd(&s_red2[lrow], v2);
            }
        }
    __syncthreads();
    if (tid < 128) {
        g_s1[m0 + tid] = s_red1[tid];
        g_s2[m0 + tid] = s_red2[tid];
    }
}

// ---------------------------------------------------------------------------
// Kernel 2: masked softmax attention + h_prime = att @ Wh (fp16 mma.sync).
// One block per (batch b, 64 i-rows): grid 256 = single wave at 2 CTA/SM.
// (unchanged from R13)
// ---------------------------------------------------------------------------
#define APAD    1040
#define B_BASE  66560
#define BSTRIDE 528
#define BSTAGE  8448
#define BCHUNK  16
#define NCHK3   (NN / BCHUNK)    // 32
#define S2_OFF  100352
#define SMEM3_T 102400

extern __shared__ char sm3[];

__device__ __forceinline__ void stage_whf(uint32_t sb, int buf, int c, int b,
                                          int tid) {
    const uint32_t dbase = sb + B_BASE + buf * BSTAGE;
#pragma unroll
    for (int i = 0; i < 2; i++) {
        const int e = tid + i * 256;          // 0..511
        const int r = e >> 5;                 // 0..15
        const int seg = e & 31;               // 0..31 (16B segs of 512B row)
        const size_t gi = ((size_t)(b * NN + c * BCHUNK + r)) * DOUT_ + seg * 8;
        CP_ASYNC16(dbase + (uint32_t)(r * BSTRIDE + seg * 16),
                   (const void*)&g_Whf[gi]);
    }
}

__global__ __launch_bounds__(256, 2)
void attn_kernel(const int* __restrict__ adj,
                 float* __restrict__ out_h,
                 float* __restrict__ out_att) {
    const uint32_t sb = smem_u32(sm3);
    float* s_s2 = (float*)(sm3 + S2_OFF);

    const int tid = threadIdx.x;
    const int wid = tid >> 5, lane = tid & 31;
    const int blk = blockIdx.x;
    const int b  = blk >> 3;           // 8 tiles of 64 rows per batch
    const int it = blk & 7;

    // Prologue: stage first 3 Wh chunks; they land while softmax runs.
    stage_whf(sb, 0, 0, b, tid); CP_COMMIT();
    stage_whf(sb, 1, 1, b, tid); CP_COMMIT();
    stage_whf(sb, 2, 2, b, tid); CP_COMMIT();

    s_s2[tid]       = g_s2[b * NN + tid];
    s_s2[tid + 256] = g_s2[b * NN + tid + 256];
    __syncthreads();

    // ---- Phase A: per-row masked leaky-relu softmax (each warp: 8 rows) ----
    for (int r = 0; r < 8; r++) {
        const int li = wid * 8 + r;            // 0..63
        const int grow = b * NN + it * 64 + li;
        const float s1i = g_s1[grow];
        const int4* arow4 = (const int4*)&adj[(size_t)grow * NN];
        float4* gatt4 = (float4*)&out_att[(size_t)grow * NN];

        float4 v[4];
        float m = -CUDART_INF_F;
#pragma unroll
        for (int c = 0; c < 4; c++) {
            const int j = c * 32 + lane;       // float4 index
            const int4  av  = arow4[j];
            const float4 s2v = *(const float4*)&s_s2[j * 4];
            float4 e;
            e.x = s1i + s2v.x; e.x = e.x > 0.f ? e.x : SLOPE * e.x;
            e.y = s1i + s2v.y; e.y = e.y > 0.f ? e.y : SLOPE * e.y;
            e.z = s1i + s2v.z; e.z = e.z > 0.f ? e.z : SLOPE * e.z;
            e.w = s1i + s2v.w; e.w = e.w > 0.f ? e.w : SLOPE * e.w;
            e.x = (av.x > 0) ? e.x : NEGV;
            e.y = (av.y > 0) ? e.y : NEGV;
            e.z = (av.z > 0) ? e.z : NEGV;
            e.w = (av.w > 0) ? e.w : NEGV;
            v[c] = e;
            m = fmaxf(m, fmaxf(fmaxf(e.x, e.y), fmaxf(e.z, e.w)));
        }
#pragma unroll
        for (int o = 16; o; o >>= 1) m = fmaxf(m, __shfl_xor_sync(0xFFFFFFFFu, m, o));

        float s = 0.f;
#pragma unroll
        for (int c = 0; c < 4; c++) {
            v[c].x = __expf(v[c].x - m);
            v[c].y = __expf(v[c].y - m);
            v[c].z = __expf(v[c].z - m);
            v[c].w = __expf(v[c].w - m);
            s += (v[c].x + v[c].y) + (v[c].z + v[c].w);
        }
#pragma unroll
        for (int o = 16; o; o >>= 1) s += __shfl_xor_sync(0xFFFFFFFFu, s, o);
        const float rinv = 1.f / s;

#pragma unroll
        for (int c = 0; c < 4; c++) {
            const int j = c * 32 + lane;
            float4 p;
            p.x = v[c].x * rinv;
            p.y = v[c].y * rinv;
            p.z = v[c].z * rinv;
            p.w = v[c].w * rinv;
            gatt4[j] = p;
            uint2 hv;
            hv.x = pack_h2(__float2half(p.x), __float2half(p.y));
            hv.y = pack_h2(__float2half(p.z), __float2half(p.w));
            *(uint2*)(sm3 + li * APAD + j * 8) = hv;
        }
    }

    // ---- Phase B: h_prime = att @ Wh_b, fp16 mma.sync ----
    const int wm = wid >> 1;           // 0..3: rows wm*16..wm*16+15
    const int wn = wid & 1;            // 0..1: cols wn*128..wn*128+127

    const int a_r = wm * 16 + (lane & 15);
    const uint32_t a_base = sb + (uint32_t)(a_r * APAD + (lane >> 4) * 16);
    const uint32_t b_off  = (uint32_t)((lane & 15) * BSTRIDE +
                                       (wn * 128 + (lane >> 4) * 8) * 2);

    float acc[16][4];
#pragma unroll
    for (int ni = 0; ni < 16; ni++)
#pragma unroll
        for (int q = 0; q < 4; q++) acc[ni][q] = 0.f;

    for (int c = 0; c < NCHK3; c++) {
        const int buf = c & 3;
        if (c < NCHK3 - 2) { CP_WAIT2(); } else { CP_WAIT0(); }
        __syncthreads();
        if (c + 3 < NCHK3) { stage_whf(sb, (c + 3) & 3, c + 3, b, tid); CP_COMMIT(); }

        uint32_t ah[4];
        LDSM_X4(ah, a_base + (uint32_t)(c * 32));          // c*16 elems * 2B

        const uint32_t bbase = sb + B_BASE + buf * BSTAGE + b_off;
#pragma unroll
        for (int g = 0; g < 8; g++) {
            uint32_t bh[4];
            LDSM_X4_T(bh, bbase + g * 32);                 // g*16 cols * 2B
            mma16816(acc[2 * g],     ah, bh[0], bh[1]);
            mma16816(acc[2 * g + 1], ah, bh[2], bh[3]);
        }
    }

    // Epilogue: write h_prime [64 x 256] tile.
    const int g = lane >> 2, t = lane & 3;
    const int rbase = b * NN + it * 64 + wm * 16;
#pragma unroll
    for (int h2 = 0; h2 < 2; h2++) {
        float* orow = &out_h[(size_t)(rbase + g + h2 * 8) * DOUT_];
#pragma unroll
        for (int ni = 0; ni < 16; ni++) {
            const int col = wn * 128 + ni * 8 + t * 2;
            float2 o;
            o.x = acc[ni][h2 * 2 + 0];
            o.y = acc[ni][h2 * 2 + 1];
            *(float2*)&orow[col] = o;
        }
    }
}

// ---------------------------------------------------------------------------
extern "C" void kernel_launch(void* const* d_in, const int* in_sizes, int n_in,
                              void* d_out, int out_size) {
    const float* h         = (const float*)d_in[0];
    const int*   adj       = (const int*)  d_in[1];
    const int*   positions = (const int*)  d_in[2];
    const float* W         = (const float*)d_in[3];
    const float* a1        = (const float*)d_in[4];
    const float* a2        = (const float*)d_in[5];
    const float* pos_table = (const float*)d_in[6];

    float* out_h   = (float*)d_out;                           // [32,512,256]
    float* out_att = (float*)d_out + (size_t)BB * NN * DOUT_; // [32,512,512]

    dim3 g0(DIN_ / 64, DOUT_ / 64);      // (12, 4)
    wt_convert_kernel<<<g0, 256>>>(W);

    cudaFuncSetAttribute(gemm_wh_mma_kernel,
                         cudaFuncAttributeMaxDynamicSharedMemorySize, GSMEM);
    gemm_wh_mma_kernel<<<MROWS / 128, 512, GSMEM>>>(h, positions, pos_table,
                                                    a1, a2);

    cudaFuncSetAttribute(attn_kernel,
                         cudaFuncAttributeMaxDynamicSharedMemorySize, SMEM3_T);
    attn_kernel<<<BB * 8, 256, SMEM3_T>>>(adj, out_h, out_att);
}

// round 16
// speedup vs baseline: 1.0620x; 1.0620x over previous
#include <cuda_runtime.h>
#include <cuda_fp16.h>
#include <math_constants.h>
#include <cstdint>

#define BB    32
#define NN    512
#define DIN_  768
#define DOUT_ 256
#define MROWS (BB * NN)          // 16384
#define NEGV  (-9.0e15f)
#define SLOPE 0.2f

// Scratch (device globals: allocation-free)
__device__ float g_s1[MROWS];
__device__ float g_s2[MROWS];
__device__ __half g_WTf[DOUT_ * DIN_];   // W^T fp16, [256][768] K-major
__device__ __half g_Whf[MROWS * DOUT_];  // Wh fp16,  [row][d]     8 MB

// ---------------------------------------------------------------------------
// Helpers
// ---------------------------------------------------------------------------
__device__ __forceinline__ uint32_t smem_u32(const void* p) {
    uint32_t a;
    asm("{ .reg .u64 t; cvta.to.shared.u64 t, %1; cvt.u32.u64 %0, t; }"
        : "=r"(a) : "l"(p));
    return a;
}

#define LDSM_X4(r, addr)                                                      \
    asm volatile("ldmatrix.sync.aligned.m8n8.x4.shared.b16 {%0,%1,%2,%3}, [%4];" \
                 : "=r"((r)[0]), "=r"((r)[1]), "=r"((r)[2]), "=r"((r)[3])     \
                 : "r"(addr))
#define LDSM_X4_T(r, addr)                                                    \
    asm volatile("ldmatrix.sync.aligned.m8n8.x4.trans.shared.b16 {%0,%1,%2,%3}, [%4];" \
                 : "=r"((r)[0]), "=r"((r)[1]), "=r"((r)[2]), "=r"((r)[3])     \
                 : "r"(addr))

__device__ __forceinline__ void mma16816(float* c, const uint32_t* a,
                                         uint32_t b0, uint32_t b1) {
    asm volatile(
        "mma.sync.aligned.m16n8k16.row.col.f32.f16.f16.f32 "
        "{%0,%1,%2,%3}, {%4,%5,%6,%7}, {%8,%9}, {%0,%1,%2,%3};"
        : "+f"(c[0]), "+f"(c[1]), "+f"(c[2]), "+f"(c[3])
        : "r"(a[0]), "r"(a[1]), "r"(a[2]), "r"(a[3]), "r"(b0), "r"(b1));
}

#define CP_ASYNC16(dst, src) \
    asm volatile("cp.async.cg.shared.global [%0], [%1], 16;" :: "r"(dst), "l"(src))
#define CP_COMMIT()  asm volatile("cp.async.commit_group;" ::: "memory")
#define CP_WAIT0()   asm volatile("cp.async.wait_group 0;" ::: "memory")
#define CP_WAIT2()   asm volatile("cp.async.wait_group 2;" ::: "memory")

__device__ __forceinline__ uint32_t pack_h2(__half a, __half b) {
    __half2 t(a, b);
    return *(uint32_t*)&t;
}

// ---------------------------------------------------------------------------
// Kernel 0: W [768,256] fp32 -> W^T fp16 [256][768] via smem tile transpose
// (64k x 64n tiles, grid (12,4), 256 threads), PLUS grid-stride zeroing of
// the s1/s2 accumulators used by the GEMM's fused atomics.
// ---------------------------------------------------------------------------
__global__ void wt_convert_kernel(const float* __restrict__ W) {
    __shared__ __half st[64][72];   // [n][k], padded
    const int tid = threadIdx.x;
    const int k0 = blockIdx.x * 64;
    const int n0 = blockIdx.y * 64;

    // Zero s1/s2: 48 blocks x 256 threads = 12288 slots for 16384 rows.
    const int flat = (blockIdx.y * gridDim.x + blockIdx.x) * 256 + tid;
    g_s1[flat] = 0.f;
    g_s2[flat] = 0.f;
    if (flat < MROWS - 12288) {
        g_s1[12288 + flat] = 0.f;
        g_s2[12288 + flat] = 0.f;
    }

#pragma unroll
    for (int i = 0; i < 4; i++) {
        const int e = tid + i * 256;          // 0..1023
        const int r  = e >> 4;                // k-row 0..63
        const int c4 = (e & 15) * 4;          // n-col 0..60
        const float4 v = *(const float4*)&W[(size_t)(k0 + r) * DOUT_ + n0 + c4];
        st[c4 + 0][r] = __float2half(v.x);
        st[c4 + 1][r] = __float2half(v.y);
        st[c4 + 2][r] = __float2half(v.z);
        st[c4 + 3][r] = __float2half(v.w);
    }
    __syncthreads();

#pragma unroll
    for (int i = 0; i < 2; i++) {
        const int e = tid + i * 256;          // 0..511
        const int n   = e >> 3;               // 0..63
        const int seg = e & 7;                // 0..7 (8 halves each)
        uint4 v;
        const __half* src = &st[n][seg * 8];
        v.x = *(const uint32_t*)&src[0];
        v.y = *(const uint32_t*)&src[2];
        v.z = *(const uint32_t*)&src[4];
        v.w = *(const uint32_t*)&src[6];
        *(uint4*)&g_WTf[(size_t)(n0 + n) * DIN_ + k0 + seg * 8] = v;
    }
}

// ---------------------------------------------------------------------------
// Kernel 1: Wh = h @ W + pos_table[positions] (fp16 mma.sync) + fused
// s1/s2 row-dots (shuffle-reduce + atomicAdd).  [R12-proven version]
// Block tile 128x128, 8 warps (4m x 2n), K-chunk 32, double-buffered smem.
// ---------------------------------------------------------------------------
#define PAD    40
#define CHUNK  32
#define NCHK   (DIN_ / CHUNK)     // 24
#define BUF_B  20480
#define GSMEM  (2 * BUF_B)        // 40960

extern __shared__ char smem_g[];

__device__ __forceinline__ void load_A_regs(const float* __restrict__ h,
                                            int m0, int kbase, int tid,
                                            float4* aR) {
#pragma unroll
    for (int i = 0; i < 4; i++) {
        const int e = tid + i * 256;          // 0..1023
        const int row = e >> 3;               // 0..127
        const int c4  = (e & 7) * 4;          // 0..28
        aR[i] = *(const float4*)&h[(size_t)(m0 + row) * DIN_ + kbase + c4];
    }
}

__device__ __forceinline__ void store_A_smem(char* s, int tid, const float4* aR) {
#pragma unroll
    for (int i = 0; i < 4; i++) {
        const int e = tid + i * 256;
        const int row = e >> 3;
        const int c4  = (e & 7) * 4;
        const float4 v = aR[i];
        uint2 hv;
        hv.x = pack_h2(__float2half(v.x), __float2half(v.y));
        hv.y = pack_h2(__float2half(v.z), __float2half(v.w));
        *(uint2*)(s + (uint32_t)(row * (PAD * 2) + c4 * 2)) = hv;
    }
}

__device__ __forceinline__ void cpasync_B(uint32_t b_byte, int n0, int kbase,
                                          int tid) {
#pragma unroll
    for (int i = 0; i < 2; i++) {
        const int e = tid + i * 256;          // 0..511
        const int row = e >> 2;               // 0..127
        const int q   = e & 3;                // 0..3
        const size_t gi = (size_t)(n0 + row) * DIN_ + kbase + q * 8;
        CP_ASYNC16(b_byte + (uint32_t)(row * (PAD * 2) + q * 16),
                   (const void*)&g_WTf[gi]);
    }
}

__global__ __launch_bounds__(256, 2)
void gemm_wh_mma_kernel(const float* __restrict__ h,
                        const int*   __restrict__ positions,
                        const float* __restrict__ pos_table,
                        const float* __restrict__ a1,
                        const float* __restrict__ a2) {
    const uint32_t sb = smem_u32(smem_g);
    const int tid  = threadIdx.x;
    const int wid  = tid >> 5;
    const int lane = tid & 31;
    const int wm = wid >> 1;           // 0..3
    const int wn = wid & 1;            // 0..1
    const int m0 = blockIdx.y * 128;
    const int n0 = blockIdx.x * 128;

    const int lr = lane & 15;
    const int lk = (lane >> 4) * 8;
    const int bn = ((lane >> 4) * 8) + (lane & 7);
    const int bk = ((lane >> 3) & 1) * 8;

    float acc[2][8][4];
#pragma unroll
    for (int mi = 0; mi < 2; mi++)
#pragma unroll
        for (int ni = 0; ni < 8; ni++)
#pragma unroll
            for (int q = 0; q < 4; q++) acc[mi][ni][q] = 0.f;

    float4 aR[4];

    cpasync_B(sb + 10240, n0, 0, tid);
    CP_COMMIT();
    load_A_regs(h, m0, 0, tid, aR);
    store_A_smem(smem_g, tid, aR);
    CP_WAIT0();
    __syncthreads();

    for (int c = 0; c < NCHK; c++) {
        const int buf  = c & 1;
        const int nbuf = buf ^ 1;

        if (c < NCHK - 1) {
            const int kn = (c + 1) * CHUNK;
            cpasync_B(sb + nbuf * BUF_B + 10240, n0, kn, tid);
            CP_COMMIT();
            load_A_regs(h, m0, kn, tid, aR);
        }

        const uint32_t AS = sb + buf * BUF_B;
        const uint32_t BS = AS + 10240;

#pragma unroll
        for (int k16 = 0; k16 < CHUNK; k16 += 16) {
            uint32_t ah[2][4];
#pragma unroll
            for (int mi = 0; mi < 2; mi++) {
                const uint32_t aa =
                    AS + (uint32_t)(((wm * 32 + mi * 16 + lr) * PAD + k16 + lk) * 2);
                LDSM_X4(ah[mi], aa);
            }
#pragma unroll
            for (int g = 0; g < 4; g++) {
                const uint32_t ba =
                    BS + (uint32_t)(((wn * 64 + g * 16 + bn) * PAD + k16 + bk) * 2);
                uint32_t bh[4];
                LDSM_X4(bh, ba);
#pragma unroll
                for (int mi = 0; mi < 2; mi++) {
                    mma16816(acc[mi][2 * g],     ah[mi], bh[0], bh[1]);
                    mma16816(acc[mi][2 * g + 1], ah[mi], bh[2], bh[3]);
                }
            }
        }

        if (c < NCHK - 1) store_A_smem(smem_g + nbuf * BUF_B, tid, aR);
        CP_WAIT0();
        __syncthreads();
    }

    // Epilogue: add pos_emb; store fp16 Wh; fused partial s1/s2 dots.
    const int g = lane >> 2, t = lane & 3;
    float p1[2][2], p2[2][2];
#pragma unroll
    for (int mi = 0; mi < 2; mi++)
#pragma unroll
        for (int h2 = 0; h2 < 2; h2++) { p1[mi][h2] = 0.f; p2[mi][h2] = 0.f; }

#pragma unroll
    for (int mi = 0; mi < 2; mi++) {
#pragma unroll
        for (int h2 = 0; h2 < 2; h2++) {
            const int row = m0 + wm * 32 + mi * 16 + g + h2 * 8;
            const int pos = positions[row];
            const float* pt = &pos_table[(size_t)pos * DOUT_];
#pragma unroll
            for (int ni = 0; ni < 8; ni++) {
                const int col = n0 + wn * 64 + ni * 8 + t * 2;
                const float2 p = *(const float2*)&pt[col];
                const float ox = acc[mi][ni][h2 * 2 + 0] + p.x;
                const float oy = acc[mi][ni][h2 * 2 + 1] + p.y;
                *(uint32_t*)&g_Whf[(size_t)row * DOUT_ + col] =
                    pack_h2(__float2half(ox), __float2half(oy));
                const float2 va1 = *(const float2*)&a1[col];
                const float2 va2 = *(const float2*)&a2[col];
                p1[mi][h2] += ox * va1.x + oy * va1.y;
                p2[mi][h2] += ox * va2.x + oy * va2.y;
            }
        }
    }
    // Reduce over the 4 t-lanes (consecutive lanes share g => same rows).
#pragma unroll
    for (int mi = 0; mi < 2; mi++)
#pragma unroll
        for (int h2 = 0; h2 < 2; h2++) {
            float v1 = p1[mi][h2], v2 = p2[mi][h2];
            v1 += __shfl_xor_sync(0xFFFFFFFFu, v1, 1);
            v1 += __shfl_xor_sync(0xFFFFFFFFu, v1, 2);
            v2 += __shfl_xor_sync(0xFFFFFFFFu, v2, 1);
            v2 += __shfl_xor_sync(0xFFFFFFFFu, v2, 2);
            if (t == 0) {
                const int row = m0 + wm * 32 + mi * 16 + g + h2 * 8;
                atomicAdd(&g_s1[row], v1);
                atomicAdd(&g_s2[row], v2);
            }
        }
}

// ---------------------------------------------------------------------------
// Kernel 2: masked softmax attention + h_prime = att @ Wh (fp16 mma.sync).
// One block per (batch b, 64 i-rows): grid 256 = single wave at 2 CTA/SM.
// (unchanged — part of the 72.4 us best run)
// ---------------------------------------------------------------------------
#define APAD    1040
#define B_BASE  66560
#define BSTRIDE 528
#define BSTAGE  8448
#define BCHUNK  16
#define NCHK3   (NN / BCHUNK)    // 32
#define S2_OFF  100352
#define SMEM3_T 102400

extern __shared__ char sm3[];

__device__ __forceinline__ void stage_whf(uint32_t sb, int buf, int c, int b,
                                          int tid) {
    const uint32_t dbase = sb + B_BASE + buf * BSTAGE;
#pragma unroll
    for (int i = 0; i < 2; i++) {
        const int e = tid + i * 256;          // 0..511
        const int r = e >> 5;                 // 0..15
        const int seg = e & 31;               // 0..31 (16B segs of 512B row)
        const size_t gi = ((size_t)(b * NN + c * BCHUNK + r)) * DOUT_ + seg * 8;
        CP_ASYNC16(dbase + (uint32_t)(r * BSTRIDE + seg * 16),
                   (const void*)&g_Whf[gi]);
    }
}

__global__ __launch_bounds__(256, 2)
void attn_kernel(const int* __restrict__ adj,
                 float* __restrict__ out_h,
                 float* __restrict__ out_att) {
    const uint32_t sb = smem_u32(sm3);
    float* s_s2 = (float*)(sm3 + S2_OFF);

    const int tid = threadIdx.x;
    const int wid = tid >> 5, lane = tid & 31;
    const int blk = blockIdx.x;
    const int b  = blk >> 3;           // 8 tiles of 64 rows per batch
    const int it = blk & 7;

    // Prologue: stage first 3 Wh chunks; they land while softmax runs.
    stage_whf(sb, 0, 0, b, tid); CP_COMMIT();
    stage_whf(sb, 1, 1, b, tid); CP_COMMIT();
    stage_whf(sb, 2, 2, b, tid); CP_COMMIT();

    s_s2[tid]       = g_s2[b * NN + tid];
    s_s2[tid + 256] = g_s2[b * NN + tid + 256];
    __syncthreads();

    // ---- Phase A: per-row masked leaky-relu softmax (each warp: 8 rows) ----
    for (int r = 0; r < 8; r++) {
        const int li = wid * 8 + r;            // 0..63
        const int grow = b * NN + it * 64 + li;
        const float s1i = g_s1[grow];
        const int4* arow4 = (const int4*)&adj[(size_t)grow * NN];
        float4* gatt4 = (float4*)&out_att[(size_t)grow * NN];

        float4 v[4];
        float m = -CUDART_INF_F;
#pragma unroll
        for (int c = 0; c < 4; c++) {
            const int j = c * 32 + lane;       // float4 index
            const int4  av  = arow4[j];
            const float4 s2v = *(const float4*)&s_s2[j * 4];
            float4 e;
            e.x = s1i + s2v.x; e.x = e.x > 0.f ? e.x : SLOPE * e.x;
            e.y = s1i + s2v.y; e.y = e.y > 0.f ? e.y : SLOPE * e.y;
            e.z = s1i + s2v.z; e.z = e.z > 0.f ? e.z : SLOPE * e.z;
            e.w = s1i + s2v.w; e.w = e.w > 0.f ? e.w : SLOPE * e.w;
            e.x = (av.x > 0) ? e.x : NEGV;
            e.y = (av.y > 0) ? e.y : NEGV;
            e.z = (av.z > 0) ? e.z : NEGV;
            e.w = (av.w > 0) ? e.w : NEGV;
            v[c] = e;
            m = fmaxf(m, fmaxf(fmaxf(e.x, e.y), fmaxf(e.z, e.w)));
        }
#pragma unroll
        for (int o = 16; o; o >>= 1) m = fmaxf(m, __shfl_xor_sync(0xFFFFFFFFu, m, o));

        float s = 0.f;
#pragma unroll
        for (int c = 0; c < 4; c++) {
            v[c].x = __expf(v[c].x - m);
            v[c].y = __expf(v[c].y - m);
            v[c].z = __expf(v[c].z - m);
            v[c].w = __expf(v[c].w - m);
            s += (v[c].x + v[c].y) + (v[c].z + v[c].w);
        }
#pragma unroll
        for (int o = 16; o; o >>= 1) s += __shfl_xor_sync(0xFFFFFFFFu, s, o);
        const float rinv = 1.f / s;

#pragma unroll
        for (int c = 0; c < 4; c++) {
            const int j = c * 32 + lane;
            float4 p;
            p.x = v[c].x * rinv;
            p.y = v[c].y * rinv;
            p.z = v[c].z * rinv;
            p.w = v[c].w * rinv;
            gatt4[j] = p;
            uint2 hv;
            hv.x = pack_h2(__float2half(p.x), __float2half(p.y));
            hv.y = pack_h2(__float2half(p.z), __float2half(p.w));
            *(uint2*)(sm3 + li * APAD + j * 8) = hv;
        }
    }

    // ---- Phase B: h_prime = att @ Wh_b, fp16 mma.sync ----
    const int wm = wid >> 1;           // 0..3: rows wm*16..wm*16+15
    const int wn = wid & 1;            // 0..1: cols wn*128..wn*128+127

    const int a_r = wm * 16 + (lane & 15);
    const uint32_t a_base = sb + (uint32_t)(a_r * APAD + (lane >> 4) * 16);
    const uint32_t b_off  = (uint32_t)((lane & 15) * BSTRIDE +
                                       (wn * 128 + (lane >> 4) * 8) * 2);

    float acc[16][4];
#pragma unroll
    for (int ni = 0; ni < 16; ni++)
#pragma unroll
        for (int q = 0; q < 4; q++) acc[ni][q] = 0.f;

    for (int c = 0; c < NCHK3; c++) {
        const int buf = c & 3;
        if (c < NCHK3 - 2) { CP_WAIT2(); } else { CP_WAIT0(); }
        __syncthreads();
        if (c + 3 < NCHK3) { stage_whf(sb, (c + 3) & 3, c + 3, b, tid); CP_COMMIT(); }

        uint32_t ah[4];
        LDSM_X4(ah, a_base + (uint32_t)(c * 32));          // c*16 elems * 2B

        const uint32_t bbase = sb + B_BASE + buf * BSTAGE + b_off;
#pragma unroll
        for (int g = 0; g < 8; g++) {
            uint32_t bh[4];
            LDSM_X4_T(bh, bbase + g * 32);                 // g*16 cols * 2B
            mma16816(acc[2 * g],     ah, bh[0], bh[1]);
            mma16816(acc[2 * g + 1], ah, bh[2], bh[3]);
        }
    }

    // Epilogue: write h_prime [64 x 256] tile.
    const int g = lane >> 2, t = lane & 3;
    const int rbase = b * NN + it * 64 + wm * 16;
#pragma unroll
    for (int h2 = 0; h2 < 2; h2++) {
        float* orow = &out_h[(size_t)(rbase + g + h2 * 8) * DOUT_];
#pragma unroll
        for (int ni = 0; ni < 16; ni++) {
            const int col = wn * 128 + ni * 8 + t * 2;
            float2 o;
            o.x = acc[ni][h2 * 2 + 0];
            o.y = acc[ni][h2 * 2 + 1];
            *(float2*)&orow[col] = o;
        }
    }
}

// ---------------------------------------------------------------------------
extern "C" void kernel_launch(void* const* d_in, const int* in_sizes, int n_in,
                              void* d_out, int out_size) {
    const float* h         = (const float*)d_in[0];
    const int*   adj       = (const int*)  d_in[1];
    const int*   positions = (const int*)  d_in[2];
    const float* W         = (const float*)d_in[3];
    const float* a1        = (const float*)d_in[4];
    const float* a2        = (const float*)d_in[5];
    const float* pos_table = (const float*)d_in[6];

    float* out_h   = (float*)d_out;                           // [32,512,256]
    float* out_att = (float*)d_out + (size_t)BB * NN * DOUT_; // [32,512,512]

    dim3 g0(DIN_ / 64, DOUT_ / 64);      // (12, 4) = 48 blocks
    wt_convert_kernel<<<g0, 256>>>(W);   // also zeroes g_s1/g_s2

    cudaFuncSetAttribute(gemm_wh_mma_kernel,
                         cudaFuncAttributeMaxDynamicSharedMemorySize, GSMEM);
    dim3 g1(DOUT_ / 128, MROWS / 128);   // (2, 128) = 256 CTAs
    gemm_wh_mma_kernel<<<g1, 256, GSMEM>>>(h, positions, pos_table, a1, a2);

    cudaFuncSetAttribute(attn_kernel,
                         cudaFuncAttributeMaxDynamicSharedMemorySize, SMEM3_T);
    attn_kernel<<<BB * 8, 256, SMEM3_T>>>(adj, out_h, out_att);
}